// round 8
// baseline (speedup 1.0000x reference)
#include <cuda_runtime.h>
#include <cuda_bf16.h>
#include <cstdint>

#define NPTS  65536
#define DIMS  512
#define KCENT 512

static __device__ __nv_bfloat16 g_cbf16[KCENT * DIMS];          // 512 KB
static __device__ float        g_csq[KCENT];                    // ||c||^2

__device__ __forceinline__ uint32_t smem_u32(const void* p) {
    uint32_t a;
    asm("{ .reg .u64 t; cvta.to.shared.u64 t, %1; cvt.u32.u64 %0, t; }"
        : "=r"(a) : "l"(p));
    return a;
}

__device__ __forceinline__ void ldsm_x4(uint32_t addr, uint32_t* r) {
    asm volatile("ldmatrix.sync.aligned.m8n8.x4.shared.b16 {%0,%1,%2,%3}, [%4];"
                 : "=r"(r[0]), "=r"(r[1]), "=r"(r[2]), "=r"(r[3]) : "r"(addr));
}

__device__ __forceinline__ void mma16816(float* d, const uint32_t* a,
                                         uint32_t b0, uint32_t b1) {
    asm volatile(
        "mma.sync.aligned.m16n8k16.row.col.f32.bf16.bf16.f32 "
        "{%0,%1,%2,%3}, {%4,%5,%6,%7}, {%8,%9}, {%0,%1,%2,%3};"
        : "+f"(d[0]), "+f"(d[1]), "+f"(d[2]), "+f"(d[3])
        : "r"(a[0]), "r"(a[1]), "r"(a[2]), "r"(a[3]), "r"(b0), "r"(b1));
}

__device__ __forceinline__ float frcp(float v) {
    float r;
    asm("rcp.approx.f32 %0, %1;" : "=f"(r) : "f"(v));
    return r;
}

// ------------------------------------------------------------------
// Prepass: centroids f32 -> bf16 + ||c||^2 (one warp per row)
// ------------------------------------------------------------------
__global__ void __launch_bounds__(256) prep_c(const float* __restrict__ c) {
    const int wid = threadIdx.x >> 5, lane = threadIdx.x & 31;
    const int row = blockIdx.x * 8 + wid;
    const float4* src = reinterpret_cast<const float4*>(c + (size_t)row * DIMS);
    uint2* dst = reinterpret_cast<uint2*>(g_cbf16 + (size_t)row * DIMS);
    float s = 0.0f;
#pragma unroll
    for (int i = 0; i < 4; i++) {
        float4 v = src[lane + i * 32];
        s = fmaf(v.x, v.x, s); s = fmaf(v.y, v.y, s);
        s = fmaf(v.z, v.z, s); s = fmaf(v.w, v.w, s);
        __nv_bfloat162 p0 = __floats2bfloat162_rn(v.x, v.y);
        __nv_bfloat162 p1 = __floats2bfloat162_rn(v.z, v.w);
        uint2 u;
        u.x = *reinterpret_cast<uint32_t*>(&p0);
        u.y = *reinterpret_cast<uint32_t*>(&p1);
        dst[lane + i * 32] = u;
    }
#pragma unroll
    for (int o = 16; o > 0; o >>= 1) s += __shfl_xor_sync(0xFFFFFFFFu, s, o);
    if (lane == 0) g_csq[row] = s;
}

// ------------------------------------------------------------------
// Main fused kernel: CTA = 64 rows x 512 cols, 512 threads (16 warps),
// warp tile 32x64. TWO K-tiles per __syncthreads (8 sync rounds total).
// 4-slot A ring (all 512 threads share the copy), 4-stage B cp.async ring.
// ------------------------------------------------------------------
#define SM_CSQ   0
#define SM_XSQ   2048
#define SM_RSUM  2304
#define SM_ARING 2560             // 4 slots x (64 rows x 80B) = 20480
#define A_SLOT   5120
#define SM_BRING 23040            // 4 stages x (512 rows x 80B) = 163840
#define B_STAGE  40960
#define ROWPITCH 80
#define SMEM_TOTAL (SM_BRING + 4 * B_STAGE)   // 186880

__global__ void __launch_bounds__(512, 1)
clu_main(const float* __restrict__ x, float* __restrict__ out) {
    extern __shared__ char smem[];
    const uint32_t sb = smem_u32(smem);
    const int tid = threadIdx.x;
    const int lane = tid & 31;
    const int wid = tid >> 5;
    const int mw = wid & 1;       // 0..1  (32 rows each)
    const int nw = wid >> 1;      // 0..7  (64 cols each)
    const int m0 = blockIdx.x * 64;

    float* csq = reinterpret_cast<float*>(smem + SM_CSQ);
    float* xsq = reinterpret_cast<float*>(smem + SM_XSQ);
    float* rsum = reinterpret_cast<float*>(smem + SM_RSUM);

    csq[tid] = g_csq[tid & 511];
    if (tid < 64) {
        xsq[tid] = 1.0f;        // becomes 1 + ||x||^2 via atomicAdd
        rsum[tid] = 0.0f;
    }

    // ---- B copy bases: 4 16B chunks per thread; offsets compile-time ----
    const __nv_bfloat16* bsrc0 =
        g_cbf16 + (size_t)(tid >> 2) * DIMS + (tid & 3) * 8;           // + i*65536 elems
    const uint32_t bdst0 = sb + SM_BRING + (tid >> 2) * ROWPITCH + (tid & 3) * 16; // + i*10240

#define ISSUE_B(stage, k0) do {                                               \
        const uint32_t _soff = (stage) * B_STAGE;                             \
        const int _koff = (k0) * 32;                                          \
        asm volatile("cp.async.cg.shared.global [%0], [%1], 16;"              \
            :: "r"(bdst0 + _soff), "l"(bsrc0 + _koff) : "memory");            \
        asm volatile("cp.async.cg.shared.global [%0], [%1], 16;"              \
            :: "r"(bdst0 + _soff + 10240), "l"(bsrc0 + _koff + 65536) : "memory"); \
        asm volatile("cp.async.cg.shared.global [%0], [%1], 16;"              \
            :: "r"(bdst0 + _soff + 20480), "l"(bsrc0 + _koff + 131072) : "memory"); \
        asm volatile("cp.async.cg.shared.global [%0], [%1], 16;"              \
            :: "r"(bdst0 + _soff + 30720), "l"(bsrc0 + _koff + 196608) : "memory"); \
        asm volatile("cp.async.commit_group;" ::: "memory");                  \
    } while (0)

    // ---- A copy: ALL 512 threads, one float4 (4 floats -> 8B bf16) each ----
    // row = tid>>3 (0..63), half = tid&7 (0..7): covers 64 x 32 f32 per K-tile
    const float* arow = x + (size_t)(m0 + (tid >> 3)) * DIMS + (tid & 7) * 4;
    const uint32_t adst = sb + SM_ARING + (tid >> 3) * ROWPITCH + (tid & 7) * 8;
    float pxsq = 0.0f;
    float4 ha0, ha1;   // held A prefetch for tiles "itp+4", "itp+5"

#define CVT_STS_A(slot, v) do {                                               \
        pxsq = fmaf((v).x, (v).x, pxsq); pxsq = fmaf((v).y, (v).y, pxsq);     \
        pxsq = fmaf((v).z, (v).z, pxsq); pxsq = fmaf((v).w, (v).w, pxsq);     \
        __nv_bfloat162 p0 = __floats2bfloat162_rn((v).x, (v).y);              \
        __nv_bfloat162 p1 = __floats2bfloat162_rn((v).z, (v).w);              \
        asm volatile("st.shared.v2.b32 [%0], {%1,%2};"                        \
                     :: "r"(adst + (slot) * A_SLOT),                          \
                        "r"(*reinterpret_cast<uint32_t*>(&p0)),               \
                        "r"(*reinterpret_cast<uint32_t*>(&p1)) : "memory");   \
    } while (0)

    // ---- prologue: A tiles 0,1 stored + 2,3 held; B stages 0,1 ----
    {
        const float4 v0 = *reinterpret_cast<const float4*>(arow);
        const float4 v1 = *reinterpret_cast<const float4*>(arow + 32);
        ha0 = *reinterpret_cast<const float4*>(arow + 64);
        ha1 = *reinterpret_cast<const float4*>(arow + 96);
        CVT_STS_A(0, v0);
        CVT_STS_A(1, v1);
    }
    ISSUE_B(0, 0);
    ISSUE_B(1, 1);

    float acc[2][8][4];
#pragma unroll
    for (int mt = 0; mt < 2; mt++)
#pragma unroll
        for (int nt = 0; nt < 8; nt++)
#pragma unroll
            for (int c = 0; c < 4; c++) acc[mt][nt][c] = 0.0f;

    // ldmatrix lane address components
    const int g = lane >> 3;
    const int row_off = (lane & 7) + (g & 1) * 8;
    const int kb = (g >> 1) * 16;
    const uint32_t a_base = sb + SM_ARING + (mw * 32 + row_off) * ROWPITCH + kb;
    const uint32_t b_base = sb + SM_BRING + (nw * 64 + row_off) * ROWPITCH + kb;

#define MMA_HALF(abuf, bA, bB, p0i) do {                                      \
        mma16816(acc[0][2*(p0i)],     (abuf)[0], (bA)[0], (bA)[2]);           \
        mma16816(acc[0][2*(p0i)+1],   (abuf)[0], (bA)[1], (bA)[3]);           \
        mma16816(acc[1][2*(p0i)],     (abuf)[1], (bA)[0], (bA)[2]);           \
        mma16816(acc[1][2*(p0i)+1],   (abuf)[1], (bA)[1], (bA)[3]);           \
        mma16816(acc[0][2*(p0i)+2],   (abuf)[0], (bB)[0], (bB)[2]);           \
        mma16816(acc[0][2*(p0i)+3],   (abuf)[0], (bB)[1], (bB)[3]);           \
        mma16816(acc[1][2*(p0i)+2],   (abuf)[1], (bB)[0], (bB)[2]);           \
        mma16816(acc[1][2*(p0i)+3],   (abuf)[1], (bB)[1], (bB)[3]);           \
    } while (0)

    // one 32-K tile: software-pipelined fragment schedule (4 half-steps)
    auto compute_tile = [&](uint32_t a_row, uint32_t b_row) {
        uint32_t aA[2][4], aB[2][4];
        uint32_t b0[4], b1[4], b2[4], b3[4], b4[4], b5[4], b6[4], b7[4];
        ldsm_x4(a_row, aA[0]);
        ldsm_x4(a_row + 16 * ROWPITCH, aA[1]);
        ldsm_x4(b_row, b0);
        ldsm_x4(b_row + 16 * ROWPITCH, b1);
        ldsm_x4(b_row + 32 * ROWPITCH, b2);
        ldsm_x4(b_row + 48 * ROWPITCH, b3);
        MMA_HALF(aA, b0, b1, 0);
        ldsm_x4(a_row + 32, aB[0]);
        ldsm_x4(a_row + 16 * ROWPITCH + 32, aB[1]);
        ldsm_x4(b_row + 32, b4);
        ldsm_x4(b_row + 16 * ROWPITCH + 32, b5);
        MMA_HALF(aA, b2, b3, 2);
        ldsm_x4(b_row + 32 * ROWPITCH + 32, b6);
        ldsm_x4(b_row + 48 * ROWPITCH + 32, b7);
        MMA_HALF(aB, b4, b5, 0);
        MMA_HALF(aB, b6, b7, 2);
    };

#pragma unroll 1
    for (int itp = 0; itp < 16; itp += 2) {
        // pending groups: {itp, itp+1}; wait until tile itp's B is resident
        asm volatile("cp.async.wait_group 1;" ::: "memory");
        __syncthreads();   // the ONLY barrier per 2 tiles

        // slots (itp+2)&3, (itp+3)&3 were read in pair itp-2 -> free now
        if (itp + 2 < 16) {
            ISSUE_B((itp + 2) & 3, itp + 2);
            ISSUE_B((itp + 3) & 3, itp + 3);
            CVT_STS_A((itp + 2) & 3, ha0);
            CVT_STS_A((itp + 3) & 3, ha1);
            if (itp + 4 < 16) {
                ha0 = *reinterpret_cast<const float4*>(arow + (itp + 4) * 32);
                ha1 = *reinterpret_cast<const float4*>(arow + (itp + 5) * 32);
            }
        }

        // tile itp
        compute_tile(a_base + (itp & 3) * A_SLOT, b_base + (itp & 3) * B_STAGE);

        // tile itp+1: wait for its B (allow the 2 just-issued groups pending)
        if (itp + 2 < 16) asm volatile("cp.async.wait_group 2;" ::: "memory");
        else              asm volatile("cp.async.wait_group 0;" ::: "memory");
        compute_tile(a_base + ((itp + 1) & 3) * A_SLOT,
                     b_base + ((itp + 1) & 3) * B_STAGE);
    }

    // finish ||x||^2: 8 partial sums per row (all 512 threads)
    atomicAdd(&xsq[tid >> 3], pxsq);
    __syncthreads();

    // ---- Epilogue: q = rcp(1 + ||x||^2 + ||c||^2 - 2 acc); rowsum; norm ----
    const int rquad = lane >> 2;
    const int cpair = (lane & 3) * 2;

#pragma unroll
    for (int mt = 0; mt < 2; mt++) {
        const float xlo = xsq[mw * 32 + mt * 16 + rquad];
        const float xhi = xsq[mw * 32 + mt * 16 + rquad + 8];
        float slo = 0.0f, shi = 0.0f;
#pragma unroll
        for (int nt = 0; nt < 8; nt++) {
            const int col = nw * 64 + nt * 8 + cpair;
            const float c0 = csq[col], c1 = csq[col + 1];
            float q0 = frcp(fmaf(-2.0f, acc[mt][nt][0], xlo + c0));
            float q1 = frcp(fmaf(-2.0f, acc[mt][nt][1], xlo + c1));
            float q2 = frcp(fmaf(-2.0f, acc[mt][nt][2], xhi + c0));
            float q3 = frcp(fmaf(-2.0f, acc[mt][nt][3], xhi + c1));
            acc[mt][nt][0] = q0; acc[mt][nt][1] = q1;
            acc[mt][nt][2] = q2; acc[mt][nt][3] = q3;
            slo += q0 + q1; shi += q2 + q3;
        }
        slo += __shfl_xor_sync(0xFFFFFFFFu, slo, 1);
        slo += __shfl_xor_sync(0xFFFFFFFFu, slo, 2);
        shi += __shfl_xor_sync(0xFFFFFFFFu, shi, 1);
        shi += __shfl_xor_sync(0xFFFFFFFFu, shi, 2);
        if ((lane & 3) == 0) {
            atomicAdd(&rsum[mw * 32 + mt * 16 + rquad], slo);
            atomicAdd(&rsum[mw * 32 + mt * 16 + rquad + 8], shi);
        }
    }
    __syncthreads();

#pragma unroll
    for (int mt = 0; mt < 2; mt++) {
        const int rlo = mw * 32 + mt * 16 + rquad;
        const float ilo = frcp(rsum[rlo]);
        const float ihi = frcp(rsum[rlo + 8]);
        float* olo = out + (size_t)(m0 + rlo) * KCENT;
        float* ohi = out + (size_t)(m0 + rlo + 8) * KCENT;
#pragma unroll
        for (int nt = 0; nt < 8; nt++) {
            const int col = nw * 64 + nt * 8 + cpair;
            float2 vlo = make_float2(acc[mt][nt][0] * ilo, acc[mt][nt][1] * ilo);
            float2 vhi = make_float2(acc[mt][nt][2] * ihi, acc[mt][nt][3] * ihi);
            *reinterpret_cast<float2*>(olo + col) = vlo;
            *reinterpret_cast<float2*>(ohi + col) = vhi;
        }
    }
}

// ------------------------------------------------------------------
extern "C" void kernel_launch(void* const* d_in, const int* in_sizes, int n_in,
                              void* d_out, int out_size) {
    (void)in_sizes; (void)n_in; (void)out_size;
    const float* x = (const float*)d_in[0];   // [65536, 512] f32
    const float* c = (const float*)d_in[1];   // [512, 512] f32
    float* out = (float*)d_out;               // [65536, 512] f32

    prep_c<<<KCENT / 8, 256>>>(c);

    static bool attr_set = false;
    if (!attr_set) {
        cudaFuncSetAttribute(clu_main, cudaFuncAttributeMaxDynamicSharedMemorySize,
                             SMEM_TOTAL);
        attr_set = true;
    }
    clu_main<<<NPTS / 64, 512, SMEM_TOTAL>>>(x, out);
}